// round 2
// baseline (speedup 1.0000x reference)
#include <cuda_runtime.h>
#include <cuda_bf16.h>
#include <cstdint>

#define S_TOT 32768
#define CH    16
#define NCHUNK (S_TOT / CH)

// ---------------- static device scratch (no runtime allocation) ----------------
__device__ float    g_fc1 [65536u * 128u];        // relu(fc) both seqs       (32 MB)
__device__ float    g_xg0 [2u * 32768u * 512u];   // layer0 input gates       (128 MB)
__device__ float    g_xg1 [2u * 32768u * 512u];   // layer1 input gates       (128 MB)
__device__ float    g_h0  [2u * 32768u * 128u];   // layer0 hidden stream     (32 MB)
__device__ float    g_y   [2u * 256u * 128u];     // last 256 h1 per seq
__device__ unsigned g_wpack[3u * 512u * 64u];     // packed bf16x2: Whh0, Wih1, Whh1
__device__ float    g_b1  [512];                  // bih1 + bhh1
__device__ int      g_prog[8];                    // progress flags

// ---------------- helpers ----------------
__device__ __forceinline__ int ld_acq(const int* p) {
    int v;
    asm volatile("ld.acquire.gpu.b32 %0, [%1];" : "=r"(v) : "l"(p) : "memory");
    return v;
}
__device__ __forceinline__ void st_rel(int* p, int v) {
    asm volatile("st.release.gpu.b32 [%0], %1;" :: "l"(p), "r"(v) : "memory");
}

__device__ __forceinline__ unsigned bf16rn_bits(float f) {
    unsigned u = __float_as_uint(f);
    return ((u + 0x7fffu + ((u >> 16) & 1u)) >> 16) & 0xffffu;
}

// Pack (w_even, w_odd): low 16 bits = bf16(w_even) (recovered by <<16).
// High 16 bits chosen so the WHOLE 32-bit word, read as fp32 (low bits are
// known garbage), best approximates w_odd -> zero-instruction odd operand.
__device__ __forceinline__ unsigned pack2(float we, float wo) {
    unsigned lo = bf16rn_bits(we);
    unsigned t  = __float_as_uint(wo) & 0xffff0000u;
    unsigned best = t | lo;
    float bd = fabsf(__uint_as_float(best) - wo);
    unsigned c = (t + 0x10000u) | lo;
    { float d = fabsf(__uint_as_float(c) - wo); if (d < bd) { bd = d; best = c; } }
    c = (t - 0x10000u) | lo;
    { float d = fabsf(__uint_as_float(c) - wo); if (d < bd) { bd = d; best = c; } }
    return best;
}

__device__ __forceinline__ float sigf(float x) {
    return __fdividef(1.0f, 1.0f + __expf(-x));
}
__device__ __forceinline__ float tanh_(float x) {
    return fmaf(2.0f, sigf(2.0f * x), -1.0f);
}

// 128-MAC dot: h (shared, fp32) . packed-bf16 row (registers)
__device__ __forceinline__ float dot128(const float* h, const unsigned* w) {
    const float4* h4 = (const float4*)h;
    float a0 = 0.f, a1 = 0.f, a2 = 0.f, a3 = 0.f;
#pragma unroll
    for (int q = 0; q < 32; q++) {
        float4 hv = h4[q];
        unsigned w01 = w[2 * q], w23 = w[2 * q + 1];
        a0 = fmaf(__uint_as_float(w01 << 16), hv.x, a0);
        a1 = fmaf(__uint_as_float(w01),       hv.y, a1);
        a2 = fmaf(__uint_as_float(w23 << 16), hv.z, a2);
        a3 = fmaf(__uint_as_float(w23),       hv.w, a3);
    }
    return (a0 + a1) + (a2 + a3);
}

// ---------------- kernel 1: pack weights, combine bias, reset flags ----------------
__global__ void __launch_bounds__(512) prep_kernel(const float* __restrict__ Wih,
                                                   const float* __restrict__ Whh,
                                                   const float* __restrict__ bih,
                                                   const float* __restrict__ bhh) {
    int wsel = blockIdx.x;   // 0: Whh L0, 1: Wih L1, 2: Whh L1
    int j = threadIdx.x;     // 512 gate rows
    const float* row;
    if (wsel == 0)      row = Whh + (size_t)j * 128;
    else if (wsel == 1) row = Wih + 512u * 128u + (size_t)j * 128;
    else                row = Whh + 512u * 128u + (size_t)j * 128;
    unsigned* dst = g_wpack + ((size_t)wsel * 512 + j) * 64;
    for (int p = 0; p < 64; p++) dst[p] = pack2(row[2 * p], row[2 * p + 1]);
    if (wsel == 1) g_b1[j] = bih[512 + j] + bhh[512 + j];
    if (wsel == 0 && j < 8) g_prog[j] = 0;
}

// ---------------- kernel 2: fc1 = relu(x @ Wfc^T + b)  M=65536 N=128 K=64 ----------------
__global__ void __launch_bounds__(256) fc1_kernel(const float* __restrict__ inp1,
                                                  const float* __restrict__ inp2,
                                                  const float* __restrict__ Wfc,
                                                  const float* __restrict__ bfc) {
    __shared__ float Ws[128][65];
    __shared__ float As[32][64];
    int tid = threadIdx.x;
    for (int i = tid; i < 128 * 64; i += 256) Ws[i >> 6][i & 63] = Wfc[i];
    int r0 = blockIdx.x * 32;
    for (int i = tid; i < 32 * 64; i += 256) {
        int r = r0 + (i >> 6), k = i & 63;
        const float* src = (r < S_TOT) ? (inp1 + (size_t)r * 64)
                                       : (inp2 + (size_t)(r - S_TOT) * 64);
        As[i >> 6][k] = src[k];
    }
    __syncthreads();
    int n = tid & 127, rb = (tid >> 7) * 16;
    float b = bfc[n];
    for (int rr = 0; rr < 16; rr++) {
        float acc = b;
#pragma unroll
        for (int k = 0; k < 64; k++) acc = fmaf(As[rb + rr][k], Ws[n][k], acc);
        g_fc1[(size_t)(r0 + rb + rr) * 128 + n] = fmaxf(acc, 0.f);
    }
}

// ---------------- kernel 3: xg0 = fc1 @ Wih0^T + (bih0+bhh0)  M=65536 N=512 K=128 ----------------
__global__ void __launch_bounds__(256) xg0_kernel(const float* __restrict__ Wih,
                                                  const float* __restrict__ bih,
                                                  const float* __restrict__ bhh) {
    __shared__ float As[64][68];   // [k][m]
    __shared__ float Bs[64][68];   // [k][n]
    int m0 = blockIdx.x * 64, n0 = blockIdx.y * 64;
    int tid = threadIdx.x;
    int tx = tid & 15, ty = tid >> 4;
    float acc[4][4] = {};
    for (int kt = 0; kt < 128; kt += 64) {
        for (int i = tid; i < 64 * 16; i += 256) {
            int r = i >> 4, c = (i & 15) * 4;
            float4 v = *(const float4*)(g_fc1 + (size_t)(m0 + r) * 128 + kt + c);
            As[c + 0][r] = v.x; As[c + 1][r] = v.y; As[c + 2][r] = v.z; As[c + 3][r] = v.w;
        }
        for (int i = tid; i < 64 * 16; i += 256) {
            int r = i >> 4, c = (i & 15) * 4;
            float4 v = *(const float4*)(Wih + (size_t)(n0 + r) * 128 + kt + c);
            Bs[c + 0][r] = v.x; Bs[c + 1][r] = v.y; Bs[c + 2][r] = v.z; Bs[c + 3][r] = v.w;
        }
        __syncthreads();
#pragma unroll
        for (int k = 0; k < 64; k++) {
            float4 a4 = *(const float4*)&As[k][ty * 4];
            float4 b4 = *(const float4*)&Bs[k][tx * 4];
            float a[4] = {a4.x, a4.y, a4.z, a4.w};
            float b[4] = {b4.x, b4.y, b4.z, b4.w};
#pragma unroll
            for (int x = 0; x < 4; x++)
#pragma unroll
                for (int y = 0; y < 4; y++) acc[x][y] = fmaf(a[x], b[y], acc[x][y]);
        }
        __syncthreads();
    }
#pragma unroll
    for (int x = 0; x < 4; x++) {
        int m = m0 + ty * 4 + x;
#pragma unroll
        for (int y = 0; y < 4; y++) {
            int n = n0 + tx * 4 + y;
            g_xg0[(size_t)m * 512 + n] = acc[x][y] + bih[n] + bhh[n];
        }
    }
}

// ---------------- persistent pipeline: recurrences + xg1 stream ----------------
__device__ __forceinline__ void lstm_rec(const float* __restrict__ xg_src,
                                         const unsigned* __restrict__ wbase,
                                         float* __restrict__ h_stream,
                                         float* __restrict__ y_out,
                                         int* wait_flag, int* set_flag) {
    __shared__ float xgs[CH][512];
    __shared__ float hsm[128];
    __shared__ float gsm[512];
    int j = threadIdx.x;
    unsigned w[64];
#pragma unroll
    for (int p = 0; p < 64; p++) w[p] = wbase[(size_t)j * 64 + p];
    if (j < 128) hsm[j] = 0.f;
    float c = 0.f;
    __syncthreads();
    for (int ck = 0; ck < NCHUNK; ck++) {
        if (wait_flag) { while (ld_acq(wait_flag) < ck + 1) {} }
        {   // stage this chunk's xg: 16x512 floats
            const float4* src4 = (const float4*)(xg_src + (size_t)ck * CH * 512);
            float4* dst4 = (float4*)&xgs[0][0];
#pragma unroll
            for (int q = 0; q < 4; q++) dst4[j + 512 * q] = src4[j + 512 * q];
        }
        __syncthreads();
#pragma unroll 1
        for (int s = 0; s < CH; s++) {
            float acc = dot128(hsm, w) + xgs[s][j];
            gsm[j] = acc;
            __syncthreads();
            if (j < 128) {
                float gi = sigf(gsm[j]);
                float gf = sigf(gsm[j + 128]);
                float gg = tanh_(gsm[j + 256]);
                float go = sigf(gsm[j + 384]);
                c = fmaf(gf, c, gi * gg);
                float h = go * tanh_(c);
                hsm[j] = h;
                int t = ck * CH + s;
                if (h_stream) h_stream[(size_t)t * 128 + j] = h;
                if (y_out && t >= S_TOT - 256)
                    y_out[(size_t)(t - (S_TOT - 256)) * 128 + j] = h;
            }
            __syncthreads();
        }
        if (set_flag && j == 0) st_rel(set_flag, ck + 1);
    }
}

__device__ __forceinline__ void xg1_producer(int seq) {
    __shared__ float h0s[CH][128];
    int j = threadIdx.x;
    const unsigned* wbase = g_wpack + 1u * 512u * 64u;
    unsigned w[64];
#pragma unroll
    for (int p = 0; p < 64; p++) w[p] = wbase[(size_t)j * 64 + p];
    float b = g_b1[j];
    const float* h0 = g_h0 + (size_t)seq * S_TOT * 128;
    float* xg1 = g_xg1 + (size_t)seq * S_TOT * 512;
    int* f0 = &g_prog[seq * 2];
    int* f1 = &g_prog[seq * 2 + 1];
    for (int ck = 0; ck < NCHUNK; ck++) {
        while (ld_acq(f0) < ck + 1) {}
        ((float4*)&h0s[0][0])[j] = ((const float4*)(h0 + (size_t)ck * CH * 128))[j];
        __syncthreads();
#pragma unroll 1
        for (int r = 0; r < CH; r++) {
            float v = dot128(&h0s[r][0], w) + b;
            xg1[(size_t)(ck * CH + r) * 512 + j] = v;
        }
        __syncthreads();
        if (j == 0) st_rel(f1, ck + 1);
    }
}

__global__ void __launch_bounds__(512, 1) pipeline_kernel() {
    int b = blockIdx.x, seq = b / 3, role = b % 3;
    if (role == 0) {
        lstm_rec(g_xg0 + (size_t)seq * S_TOT * 512, g_wpack,
                 g_h0 + (size_t)seq * S_TOT * 128, nullptr,
                 nullptr, &g_prog[seq * 2]);
    } else if (role == 1) {
        xg1_producer(seq);
    } else {
        lstm_rec(g_xg1 + (size_t)seq * S_TOT * 512, g_wpack + 2u * 512u * 64u,
                 nullptr, g_y + (size_t)seq * 256u * 128u,
                 &g_prog[seq * 2 + 1], nullptr);
    }
}

// ---------------- head: p = softmax([W r12, W r21, W (r12-r21)] + b) ----------------
__global__ void __launch_bounds__(256) head_kernel(const float* __restrict__ Wh,
                                                   const float* __restrict__ bh,
                                                   float* __restrict__ out) {
    int r = threadIdx.x;
    const float* y1 = g_y + (size_t)r * 128;
    const float* y2 = g_y + 256u * 128u + (size_t)r * 128;
    float s1 = 0.f, s2 = 0.f;
#pragma unroll 8
    for (int k = 0; k < 128; k++) {
        float d = y1[k] - y2[k];
        float w = Wh[k];
        s1 = fmaf(w, fmaxf(d, 0.f), s1);
        s2 = fmaf(w, fmaxf(-d, 0.f), s2);
    }
    float b = bh[0];
    float p1 = s1 + b, p2 = s2 + b, pd = (s1 - s2) + b;
    float m = fmaxf(p1, fmaxf(p2, pd));
    float e1 = expf(p1 - m), e2 = expf(p2 - m), e3 = expf(pd - m);
    float inv = 1.f / (e1 + e2 + e3);
    out[r * 3 + 0] = e1 * inv;
    out[r * 3 + 1] = e2 * inv;
    out[r * 3 + 2] = e3 * inv;
}

// ---------------- launch ----------------
extern "C" void kernel_launch(void* const* d_in, const int* in_sizes, int n_in,
                              void* d_out, int out_size) {
    const float* inp1  = (const float*)d_in[0];
    const float* inp2  = (const float*)d_in[1];
    const float* Wfc   = (const float*)d_in[2];
    const float* bfc   = (const float*)d_in[3];
    const float* Wih   = (const float*)d_in[4];
    const float* Whh   = (const float*)d_in[5];
    const float* bih   = (const float*)d_in[6];
    const float* bhh   = (const float*)d_in[7];
    const float* Whead = (const float*)d_in[8];
    const float* bhead = (const float*)d_in[9];
    float* out = (float*)d_out;

    prep_kernel<<<3, 512>>>(Wih, Whh, bih, bhh);
    fc1_kernel<<<2048, 256>>>(inp1, inp2, Wfc, bfc);
    xg0_kernel<<<dim3(1024, 8), 256>>>(Wih, bih, bhh);
    pipeline_kernel<<<6, 512>>>();
    head_kernel<<<1, 256>>>(Whead, bhead, out);
}